// round 6
// baseline (speedup 1.0000x reference)
#include <cuda_runtime.h>
#include <cstdint>

#define NN 50000
#define BB 512
#define DD 32
#define NSAMP 1001
#define GY 8                 // batch replication of lambda grid
#define ROWS 64              // BB / GY rows per lambda block
#define NBX 49               // ceil((NN/4)/256)
#define NB_LAMBDA (NBX * GY) // 392
#define L2E 1.4426950408889634f
#define LN2 0.6931471805599453f

// Scratch (no cudaMalloc allowed)
__device__ float4 g_bc[BB];                 // (Ecs, Ecd, psln_signed_by_et, unused)
__device__ float  g_psiB[BB], g_kB[BB];
__device__ float  g_gBase[BB], g_alphaB[BB], g_wtB[BB];

// ---------------------------------------------------------------------------
// Kernel 1: per-batch constants. 8 lanes per item, 32 items per block.
// ---------------------------------------------------------------------------
__global__ void __launch_bounds__(256) bconst_kernel(
    const float* __restrict__ emb, const int* __restrict__ assoc,
    const int* __restrict__ src, const int* __restrict__ pos_dst,
    const float* __restrict__ last_update, const float* __restrict__ cur_time,
    const int* __restrict__ et, const float* __restrict__ W,
    const float* __restrict__ bvec, const float* __restrict__ psi,
    const float* __restrict__ alpha, const float* __restrict__ w_t)
{
    __shared__ float sW[128];  // raw W, (2, 64) row-major
    int tid = threadIdx.x;
    if (tid < 128) sW[tid] = W[tid];
    __syncthreads();

    int idx = blockIdx.x * 32 + (tid >> 3);
    int r   = tid & 7;
    if (idx >= BB) return;

    int e = (et[idx] > 0) ? 1 : 0;
    int s = assoc[src[idx]];
    int d = assoc[pos_dst[idx]];

    float4 zs4 = *(const float4*)(emb + (size_t)s * DD + r * 4);
    float4 zd4 = *(const float4*)(emb + (size_t)d * DD + r * 4);

    const float* Wu = sW + e * 64 + r * 4;
    const float* Wv = sW + e * 64 + 32 + r * 4;
    float dus = zs4.x*Wu[0] + zs4.y*Wu[1] + zs4.z*Wu[2] + zs4.w*Wu[3];
    float dvd = zd4.x*Wv[0] + zd4.y*Wv[1] + zd4.z*Wv[2] + zd4.w*Wv[3];

    #pragma unroll
    for (int off = 1; off <= 4; off <<= 1) {
        dus += __shfl_xor_sync(0xffffffffu, dus, off);
        dvd += __shfl_xor_sync(0xffffffffu, dvd, off);
    }

    if (r == 0) {
        float ct  = cur_time[idx];
        float tds = (ct - last_update[s]) * (1.0f / 100.0f);
        float tdd = (ct - last_update[d]) * (1.0f / 100.0f);
        float be = bvec[e], al = alpha[e], wt = w_t[e], ps = psi[e];
        float k  = 1.0f / (ps + 1e-7f);
        float kl = k * L2E;
        float cs = dus + be + al * expf(-wt * tds);
        float cd = dvd + be + al * expf(-wt * tdd);

        float4 bc;
        bc.x = exp2f(kl * cs);
        bc.y = exp2f(kl * cd);
        float psln = ps * LN2;
        bc.z = e ? -psln : psln;
        bc.w = 0.0f;
        g_bc[idx] = bc;

        // rtp constants
        g_gBase[idx]  = dus + dvd + be;
        g_psiB[idx]   = ps;
        g_kB[idx]     = k;
        g_alphaB[idx] = al;
        g_wtB[idx]    = wt;
    }
}

// ---------------------------------------------------------------------------
// Kernel 2: blocks [0, BB) do return_time_pred; blocks [BB, BB+NB_LAMBDA) do
// the 2 x (512, 50000) lambda arrays with fused node-dot prologue.
// ---------------------------------------------------------------------------
__global__ void __launch_bounds__(256) main_kernel(
    const float* __restrict__ emb, const float* __restrict__ psi,
    const float* __restrict__ W, float* __restrict__ out)
{
    int bx  = blockIdx.x;
    int tid = threadIdx.x;

    if (bx < BB) {
        // ------------------- return_time_pred (per-b block scan) -----------
        int b    = bx;
        int lane = tid & 31;
        int wid  = tid >> 5;

        __shared__ float warpSums[8];
        __shared__ float sLast;

        float gb = g_gBase[b], al = g_alphaB[b], wt = g_wtB[b];
        float ps = g_psiB[b],  k  = g_kB[b];

        float carry = 0.0f, acc = 0.0f;

        for (int c = 0; c < 4; c++) {
            int   s  = c * 256 + tid;
            float td = (float)s * 0.01f;
            float x = 0.0f, inten = 0.0f;
            if (s < NSAMP) {
                float g  = gb + al * __expf(-wt * (td * (1.0f / 100.0f)));
                float gp = g * k;
                inten = ps * (fmaxf(gp, 0.0f) + __logf(1.0f + __expf(-fabsf(gp))));
                x = 0.01f * inten;
            }
            float v = x;
            #pragma unroll
            for (int off = 1; off < 32; off <<= 1) {
                float t = __shfl_up_sync(0xffffffffu, v, off);
                if (lane >= off) v += t;
            }
            if (lane == 31) warpSums[wid] = v;
            __syncthreads();
            if (tid < 8) {
                float wv = warpSums[tid];
                #pragma unroll
                for (int off = 1; off < 8; off <<= 1) {
                    float t = __shfl_up_sync(0xffu, wv, off);
                    if (tid >= off) wv += t;
                }
                warpSums[tid] = wv;
            }
            __syncthreads();
            float incl     = v + (wid ? warpSums[wid - 1] : 0.0f);
            float chunkSum = warpSums[7];

            if (s < NSAMP) {
                float integral = carry + incl;
                float density  = inten * __expf(-integral);
                float ts       = td * density;
                acc += ts;
                if (s == NSAMP - 1) sLast = ts;
            }
            carry += chunkSum;
            __syncthreads();
        }

        #pragma unroll
        for (int off = 16; off; off >>= 1)
            acc += __shfl_down_sync(0xffffffffu, acc, off);
        if (lane == 0) warpSums[wid] = acc;
        __syncthreads();
        if (tid == 0) {
            float tot = 0.0f;
            #pragma unroll
            for (int i = 0; i < 8; i++) tot += warpSums[i];
            out[(size_t)2 * BB * NN + b] = 0.01f * (tot - 0.5f * sLast);
        }
        return;
    }

    // ------------------------- lambda arrays -------------------------------
    int lb = bx - BB;
    int gx = lb % NBX;
    int gy = lb / NBX;

    __shared__ __align__(16) float  sW[128];   // W pre-scaled by k_e * log2(e)
    __shared__ float4 sBC[ROWS];

    if (tid < 128) {
        float kl = L2E / (psi[tid >> 6] + 1e-7f);
        sW[tid] = W[tid] * kl;
    }
    if (tid < ROWS) sBC[tid] = g_bc[gy * ROWS + tid];
    __syncthreads();

    int n4 = gx * 256 + tid;
    if (n4 >= NN / 4) return;

    // Prologue: E[m] = 2^(k_e*log2e*dot) for the 4 owned nodes.
    // E[m] = (Eu0, Eu1, Ev0, Ev1)
    float4 E[4];
    #pragma unroll
    for (int m = 0; m < 4; m++) {
        const float4* row = (const float4*)(emb + (size_t)(n4 * 4 + m) * DD);
        float u0 = 0.f, u1 = 0.f, v0 = 0.f, v1 = 0.f;
        #pragma unroll
        for (int i = 0; i < 8; i++) {
            float4 e4 = row[i];
            float4 a0 = *(const float4*)(sW +      i * 4);   // Wu0*kl0
            float4 a1 = *(const float4*)(sW + 32 + i * 4);   // Wv0*kl0
            float4 a2 = *(const float4*)(sW + 64 + i * 4);   // Wu1*kl1
            float4 a3 = *(const float4*)(sW + 96 + i * 4);   // Wv1*kl1
            u0 += e4.x*a0.x + e4.y*a0.y + e4.z*a0.z + e4.w*a0.w;
            v0 += e4.x*a1.x + e4.y*a1.y + e4.z*a1.z + e4.w*a1.w;
            u1 += e4.x*a2.x + e4.y*a2.y + e4.z*a2.z + e4.w*a2.w;
            v1 += e4.x*a3.x + e4.y*a3.y + e4.z*a3.z + e4.w*a3.w;
        }
        E[m] = make_float4(exp2f(u0), exp2f(u1), exp2f(v0), exp2f(v1));
    }

    const size_t dstOff = (size_t)BB * NN;
    const size_t nbase  = (size_t)n4 * 4;
    const int    b0     = gy * ROWS;

    #pragma unroll 4
    for (int j = 0; j < ROWS; j++) {
        float4 bc = sBC[j];
        float pl   = bc.z;
        bool  e    = (pl < 0.0f);
        float psln = fabsf(pl);
        float Ecs  = bc.x, Ecd = bc.y;

        float4 rs, rd;
        {
            float Ev = e ? E[0].w : E[0].z, Eu = e ? E[0].y : E[0].x;
            rs.x = psln * __log2f(fmaf(Ecs, Ev, 1.0f));
            rd.x = psln * __log2f(fmaf(Ecd, Eu, 1.0f));
        }
        {
            float Ev = e ? E[1].w : E[1].z, Eu = e ? E[1].y : E[1].x;
            rs.y = psln * __log2f(fmaf(Ecs, Ev, 1.0f));
            rd.y = psln * __log2f(fmaf(Ecd, Eu, 1.0f));
        }
        {
            float Ev = e ? E[2].w : E[2].z, Eu = e ? E[2].y : E[2].x;
            rs.z = psln * __log2f(fmaf(Ecs, Ev, 1.0f));
            rd.z = psln * __log2f(fmaf(Ecd, Eu, 1.0f));
        }
        {
            float Ev = e ? E[3].w : E[3].z, Eu = e ? E[3].y : E[3].x;
            rs.w = psln * __log2f(fmaf(Ecs, Ev, 1.0f));
            rd.w = psln * __log2f(fmaf(Ecd, Eu, 1.0f));
        }

        size_t base = (size_t)(b0 + j) * NN + nbase;
        __stcs((float4*)(out + base), rs);
        __stcs((float4*)(out + dstOff + base), rd);
    }
}

// ---------------------------------------------------------------------------
extern "C" void kernel_launch(void* const* d_in, const int* in_sizes, int n_in,
                              void* d_out, int out_size)
{
    const float* emb         = (const float*)d_in[0];
    const int*   assoc       = (const int*)  d_in[1];
    const int*   src         = (const int*)  d_in[2];
    const int*   pos_dst     = (const int*)  d_in[3];
    // d_in[4] = neg_dst (unused by reference)
    const float* last_update = (const float*)d_in[5];
    const float* cur_time    = (const float*)d_in[6];
    const int*   et          = (const int*)  d_in[7];
    const float* W           = (const float*)d_in[8];
    const float* bvec        = (const float*)d_in[9];
    const float* psi         = (const float*)d_in[10];
    const float* alpha       = (const float*)d_in[11];
    const float* w_t         = (const float*)d_in[12];

    float* out = (float*)d_out;

    bconst_kernel<<<BB / 32, 256>>>(
        emb, assoc, src, pos_dst, last_update, cur_time, et,
        W, bvec, psi, alpha, w_t);

    main_kernel<<<BB + NB_LAMBDA, 256>>>(emb, psi, W, out);
}

// round 7
// speedup vs baseline: 1.3204x; 1.3204x over previous
#include <cuda_runtime.h>
#include <cstdint>

#define NN 50000
#define BB 512
#define DD 32
#define NSAMP 1001
#define BTILE 16
#define NBX 49                    // ceil((NN/4)/256)
#define GYN 32                    // BB / BTILE
#define NB_LAMBDA (NBX * GYN)     // 1568
#define L2E 1.4426950408889634f
#define LN2 0.6931471805599453f

// Scratch (no cudaMalloc allowed)
__device__ float4 g_nodeE[NN];    // (Eu0, Eu1, Ev0, Ev1) = 2^(kl_e * dot)
__device__ float4 g_bc[BB];       // (Ecs, Ecd, psln signed by et, unused)
__device__ float  g_psiB[BB], g_kB[BB];
__device__ float  g_gBase[BB], g_alphaB[BB], g_wtB[BB];

// ---------------------------------------------------------------------------
// Kernel 1: node exp-factors (8 lanes per node) + per-batch constants
// (8 lanes per item, appended blocks).
// ---------------------------------------------------------------------------
__global__ void __launch_bounds__(256) precompute_kernel(
    const float* __restrict__ emb, const int* __restrict__ assoc,
    const int* __restrict__ src, const int* __restrict__ pos_dst,
    const float* __restrict__ last_update, const float* __restrict__ cur_time,
    const int* __restrict__ et, const float* __restrict__ W,
    const float* __restrict__ bvec, const float* __restrict__ psi,
    const float* __restrict__ alpha, const float* __restrict__ w_t,
    int nodeBlocks)
{
    __shared__ float sW[128];  // node blocks: W pre-scaled by kl_e; bconst: raw W
    int tid = threadIdx.x;

    if ((int)blockIdx.x < nodeBlocks) {
        if (tid < 128) {
            float kl = L2E / (psi[tid >> 6] + 1e-7f);
            sW[tid] = W[tid] * kl;
        }
        __syncthreads();

        int g = blockIdx.x * 256 + tid;
        if (g >= NN * 8) return;
        int n = g >> 3;
        int r = g & 7;

        float4 e4 = *(const float4*)(emb + (size_t)n * DD + r * 4);

        // component c: 0->Wu0*kl0, 1->Wu1*kl1, 2->Wv0*kl0, 3->Wv1*kl1
        const float* w0 = sW +      r * 4;   // Wu0
        const float* w1 = sW + 64 + r * 4;   // Wu1
        const float* w2 = sW + 32 + r * 4;   // Wv0
        const float* w3 = sW + 96 + r * 4;   // Wv1
        float p0 = e4.x*w0[0] + e4.y*w0[1] + e4.z*w0[2] + e4.w*w0[3];
        float p1 = e4.x*w1[0] + e4.y*w1[1] + e4.z*w1[2] + e4.w*w1[3];
        float p2 = e4.x*w2[0] + e4.y*w2[1] + e4.z*w2[2] + e4.w*w2[3];
        float p3 = e4.x*w3[0] + e4.y*w3[1] + e4.z*w3[2] + e4.w*w3[3];

        #pragma unroll
        for (int off = 1; off <= 4; off <<= 1) {
            p0 += __shfl_xor_sync(0xffffffffu, p0, off);
            p1 += __shfl_xor_sync(0xffffffffu, p1, off);
            p2 += __shfl_xor_sync(0xffffffffu, p2, off);
            p3 += __shfl_xor_sync(0xffffffffu, p3, off);
        }
        if (r < 4) {
            float v = (r == 0) ? p0 : (r == 1) ? p1 : (r == 2) ? p2 : p3;
            ((float*)g_nodeE)[n * 4 + r] = exp2f(v);
        }
    } else {
        if (tid < 128) sW[tid] = W[tid];
        __syncthreads();

        int idx = (blockIdx.x - nodeBlocks) * 32 + (tid >> 3);
        int r   = tid & 7;
        if (idx >= BB) return;

        int e = (et[idx] > 0) ? 1 : 0;
        int s = assoc[src[idx]];
        int d = assoc[pos_dst[idx]];

        float4 zs4 = *(const float4*)(emb + (size_t)s * DD + r * 4);
        float4 zd4 = *(const float4*)(emb + (size_t)d * DD + r * 4);

        const float* Wu = sW + e * 64 + r * 4;
        const float* Wv = sW + e * 64 + 32 + r * 4;
        float dus = zs4.x*Wu[0] + zs4.y*Wu[1] + zs4.z*Wu[2] + zs4.w*Wu[3];
        float dvd = zd4.x*Wv[0] + zd4.y*Wv[1] + zd4.z*Wv[2] + zd4.w*Wv[3];

        #pragma unroll
        for (int off = 1; off <= 4; off <<= 1) {
            dus += __shfl_xor_sync(0xffffffffu, dus, off);
            dvd += __shfl_xor_sync(0xffffffffu, dvd, off);
        }

        if (r == 0) {
            float ct  = cur_time[idx];
            float tds = (ct - last_update[s]) * (1.0f / 100.0f);
            float tdd = (ct - last_update[d]) * (1.0f / 100.0f);
            float be = bvec[e], al = alpha[e], wt = w_t[e], ps = psi[e];
            float k  = 1.0f / (ps + 1e-7f);
            float kl = k * L2E;
            float cs = dus + be + al * expf(-wt * tds);
            float cd = dvd + be + al * expf(-wt * tdd);

            float4 bc;
            bc.x = exp2f(kl * cs);
            bc.y = exp2f(kl * cd);
            float psln = ps * LN2;
            bc.z = e ? -psln : psln;
            bc.w = 0.0f;
            g_bc[idx] = bc;

            g_gBase[idx]  = dus + dvd + be;
            g_psiB[idx]   = ps;
            g_kB[idx]     = k;
            g_alphaB[idx] = al;
            g_wtB[idx]    = wt;
        }
    }
}

// ---------------------------------------------------------------------------
// Kernel 2: blocks [0, NB_LAMBDA) = lambda arrays (BTILE=16 batch rows each);
// blocks [NB_LAMBDA, NB_LAMBDA+BB) = return_time_pred.
// ---------------------------------------------------------------------------
__global__ void __launch_bounds__(256) main_kernel(float* __restrict__ out)
{
    int bx  = blockIdx.x;
    int tid = threadIdx.x;

    if (bx < NB_LAMBDA) {
        // ------------------------- lambda arrays ---------------------------
        int gx = bx % NBX;
        int gy = bx / NBX;

        __shared__ float4 sBC[BTILE];
        if (tid < BTILE) sBC[tid] = g_bc[gy * BTILE + tid];
        __syncthreads();

        int n4 = gx * 256 + tid;
        if (n4 >= NN / 4) return;

        float4 E0 = g_nodeE[n4 * 4 + 0];
        float4 E1 = g_nodeE[n4 * 4 + 1];
        float4 E2 = g_nodeE[n4 * 4 + 2];
        float4 E3 = g_nodeE[n4 * 4 + 3];

        const size_t dstOff = (size_t)BB * NN;
        const size_t nbase  = (size_t)n4 * 4;
        const int    b0     = gy * BTILE;

        #pragma unroll 4
        for (int j = 0; j < BTILE; j++) {
            float4 bc = sBC[j];
            float pl   = bc.z;
            bool  e    = (pl < 0.0f);
            float psln = fabsf(pl);
            float Ecs  = bc.x, Ecd = bc.y;

            float4 rs, rd;
            {
                float Ev = e ? E0.w : E0.z, Eu = e ? E0.y : E0.x;
                rs.x = psln * __log2f(fmaf(Ecs, Ev, 1.0f));
                rd.x = psln * __log2f(fmaf(Ecd, Eu, 1.0f));
            }
            {
                float Ev = e ? E1.w : E1.z, Eu = e ? E1.y : E1.x;
                rs.y = psln * __log2f(fmaf(Ecs, Ev, 1.0f));
                rd.y = psln * __log2f(fmaf(Ecd, Eu, 1.0f));
            }
            {
                float Ev = e ? E2.w : E2.z, Eu = e ? E2.y : E2.x;
                rs.z = psln * __log2f(fmaf(Ecs, Ev, 1.0f));
                rd.z = psln * __log2f(fmaf(Ecd, Eu, 1.0f));
            }
            {
                float Ev = e ? E3.w : E3.z, Eu = e ? E3.y : E3.x;
                rs.w = psln * __log2f(fmaf(Ecs, Ev, 1.0f));
                rd.w = psln * __log2f(fmaf(Ecd, Eu, 1.0f));
            }

            size_t base = (size_t)(b0 + j) * NN + nbase;
            __stcs((float4*)(out + base), rs);
            __stcs((float4*)(out + dstOff + base), rd);
        }
        return;
    }

    // ------------------- return_time_pred (per-b block scan) ---------------
    int b    = bx - NB_LAMBDA;
    int lane = tid & 31;
    int wid  = tid >> 5;

    __shared__ float warpSums[8];
    __shared__ float sLast;

    float gb = g_gBase[b], al = g_alphaB[b], wt = g_wtB[b];
    float ps = g_psiB[b],  k  = g_kB[b];

    float carry = 0.0f, acc = 0.0f;

    for (int c = 0; c < 4; c++) {
        int   s  = c * 256 + tid;
        float td = (float)s * 0.01f;
        float x = 0.0f, inten = 0.0f;
        if (s < NSAMP) {
            float g  = gb + al * __expf(-wt * (td * (1.0f / 100.0f)));
            float gp = g * k;
            inten = ps * (fmaxf(gp, 0.0f) + __logf(1.0f + __expf(-fabsf(gp))));
            x = 0.01f * inten;
        }
        float v = x;
        #pragma unroll
        for (int off = 1; off < 32; off <<= 1) {
            float t = __shfl_up_sync(0xffffffffu, v, off);
            if (lane >= off) v += t;
        }
        if (lane == 31) warpSums[wid] = v;
        __syncthreads();
        if (tid < 8) {
            float wv = warpSums[tid];
            #pragma unroll
            for (int off = 1; off < 8; off <<= 1) {
                float t = __shfl_up_sync(0xffu, wv, off);
                if (tid >= off) wv += t;
            }
            warpSums[tid] = wv;
        }
        __syncthreads();
        float incl     = v + (wid ? warpSums[wid - 1] : 0.0f);
        float chunkSum = warpSums[7];

        if (s < NSAMP) {
            float integral = carry + incl;
            float density  = inten * __expf(-integral);
            float ts       = td * density;
            acc += ts;
            if (s == NSAMP - 1) sLast = ts;
        }
        carry += chunkSum;
        __syncthreads();
    }

    #pragma unroll
    for (int off = 16; off; off >>= 1)
        acc += __shfl_down_sync(0xffffffffu, acc, off);
    if (lane == 0) warpSums[wid] = acc;
    __syncthreads();
    if (tid == 0) {
        float tot = 0.0f;
        #pragma unroll
        for (int i = 0; i < 8; i++) tot += warpSums[i];
        out[(size_t)2 * BB * NN + b] = 0.01f * (tot - 0.5f * sLast);
    }
}

// ---------------------------------------------------------------------------
extern "C" void kernel_launch(void* const* d_in, const int* in_sizes, int n_in,
                              void* d_out, int out_size)
{
    const float* emb         = (const float*)d_in[0];
    const int*   assoc       = (const int*)  d_in[1];
    const int*   src         = (const int*)  d_in[2];
    const int*   pos_dst     = (const int*)  d_in[3];
    // d_in[4] = neg_dst (unused by reference)
    const float* last_update = (const float*)d_in[5];
    const float* cur_time    = (const float*)d_in[6];
    const int*   et          = (const int*)  d_in[7];
    const float* W           = (const float*)d_in[8];
    const float* bvec        = (const float*)d_in[9];
    const float* psi         = (const float*)d_in[10];
    const float* alpha       = (const float*)d_in[11];
    const float* w_t         = (const float*)d_in[12];

    float* out = (float*)d_out;

    int nodeBlocks = (NN * 8 + 255) / 256;   // 1563 (8 lanes per node)
    int bBlocks    = (BB + 31) / 32;         // 16
    precompute_kernel<<<nodeBlocks + bBlocks, 256>>>(
        emb, assoc, src, pos_dst, last_update, cur_time, et,
        W, bvec, psi, alpha, w_t, nodeBlocks);

    main_kernel<<<NB_LAMBDA + BB, 256>>>(out);
}

// round 8
// speedup vs baseline: 1.3427x; 1.0169x over previous
#include <cuda_runtime.h>
#include <cstdint>

#define NN 50000
#define BB 512
#define DD 32
#define NSAMP 1001
#define BTILE 16
#define NBX 49                    // ceil((NN/4)/256)
#define GYN 32                    // BB / BTILE
#define NB_LAMBDA (NBX * GYN)     // 1568
#define L2E 1.4426950408889634f
#define LN2 0.6931471805599453f

// Scratch (no cudaMalloc allowed)
__device__ float4 g_nodeE[NN];    // (Eu0, Eu1, Ev0, Ev1) = 2^(kl_e * dot)
__device__ float4 g_bc[BB];       // (Ecs, Ecd, psln signed by et, unused)
__device__ float  g_psiB[BB], g_kB[BB];
__device__ float  g_gBase[BB], g_alphaB[BB], g_wtB[BB];

// ---------------------------------------------------------------------------
// Kernel 1: node exp-factors (8 lanes per node) + per-batch constants
// (8 lanes per item, appended blocks).
// ---------------------------------------------------------------------------
__global__ void __launch_bounds__(256) precompute_kernel(
    const float* __restrict__ emb, const int* __restrict__ assoc,
    const int* __restrict__ src, const int* __restrict__ pos_dst,
    const float* __restrict__ last_update, const float* __restrict__ cur_time,
    const int* __restrict__ et, const float* __restrict__ W,
    const float* __restrict__ bvec, const float* __restrict__ psi,
    const float* __restrict__ alpha, const float* __restrict__ w_t,
    int nodeBlocks)
{
    __shared__ float sW[128];  // node blocks: W pre-scaled by kl_e; bconst: raw W
    int tid = threadIdx.x;

    if ((int)blockIdx.x < nodeBlocks) {
        if (tid < 128) {
            float kl = L2E / (psi[tid >> 6] + 1e-7f);
            sW[tid] = W[tid] * kl;
        }
        __syncthreads();

        int g = blockIdx.x * 256 + tid;
        if (g >= NN * 8) return;
        int n = g >> 3;
        int r = g & 7;

        float4 e4 = *(const float4*)(emb + (size_t)n * DD + r * 4);

        // component c: 0->Wu0*kl0, 1->Wu1*kl1, 2->Wv0*kl0, 3->Wv1*kl1
        const float* w0 = sW +      r * 4;   // Wu0
        const float* w1 = sW + 64 + r * 4;   // Wu1
        const float* w2 = sW + 32 + r * 4;   // Wv0
        const float* w3 = sW + 96 + r * 4;   // Wv1
        float p0 = e4.x*w0[0] + e4.y*w0[1] + e4.z*w0[2] + e4.w*w0[3];
        float p1 = e4.x*w1[0] + e4.y*w1[1] + e4.z*w1[2] + e4.w*w1[3];
        float p2 = e4.x*w2[0] + e4.y*w2[1] + e4.z*w2[2] + e4.w*w2[3];
        float p3 = e4.x*w3[0] + e4.y*w3[1] + e4.z*w3[2] + e4.w*w3[3];

        #pragma unroll
        for (int off = 1; off <= 4; off <<= 1) {
            p0 += __shfl_xor_sync(0xffffffffu, p0, off);
            p1 += __shfl_xor_sync(0xffffffffu, p1, off);
            p2 += __shfl_xor_sync(0xffffffffu, p2, off);
            p3 += __shfl_xor_sync(0xffffffffu, p3, off);
        }
        if (r < 4) {
            float v = (r == 0) ? p0 : (r == 1) ? p1 : (r == 2) ? p2 : p3;
            ((float*)g_nodeE)[n * 4 + r] = exp2f(v);
        }
    } else {
        if (tid < 128) sW[tid] = W[tid];
        __syncthreads();

        int idx = (blockIdx.x - nodeBlocks) * 32 + (tid >> 3);
        int r   = tid & 7;
        if (idx >= BB) return;

        int e = (et[idx] > 0) ? 1 : 0;
        int s = assoc[src[idx]];
        int d = assoc[pos_dst[idx]];

        float4 zs4 = *(const float4*)(emb + (size_t)s * DD + r * 4);
        float4 zd4 = *(const float4*)(emb + (size_t)d * DD + r * 4);

        const float* Wu = sW + e * 64 + r * 4;
        const float* Wv = sW + e * 64 + 32 + r * 4;
        float dus = zs4.x*Wu[0] + zs4.y*Wu[1] + zs4.z*Wu[2] + zs4.w*Wu[3];
        float dvd = zd4.x*Wv[0] + zd4.y*Wv[1] + zd4.z*Wv[2] + zd4.w*Wv[3];

        #pragma unroll
        for (int off = 1; off <= 4; off <<= 1) {
            dus += __shfl_xor_sync(0xffffffffu, dus, off);
            dvd += __shfl_xor_sync(0xffffffffu, dvd, off);
        }

        if (r == 0) {
            float ct  = cur_time[idx];
            float tds = (ct - last_update[s]) * (1.0f / 100.0f);
            float tdd = (ct - last_update[d]) * (1.0f / 100.0f);
            float be = bvec[e], al = alpha[e], wt = w_t[e], ps = psi[e];
            float k  = 1.0f / (ps + 1e-7f);
            float kl = k * L2E;
            float cs = dus + be + al * expf(-wt * tds);
            float cd = dvd + be + al * expf(-wt * tdd);

            float4 bc;
            bc.x = exp2f(kl * cs);
            bc.y = exp2f(kl * cd);
            float psln = ps * LN2;
            bc.z = e ? -psln : psln;
            bc.w = 0.0f;
            g_bc[idx] = bc;

            g_gBase[idx]  = dus + dvd + be;
            g_psiB[idx]   = ps;
            g_kB[idx]     = k;
            g_alphaB[idx] = al;
            g_wtB[idx]    = wt;
        }
    }
}

// ---------------------------------------------------------------------------
// Kernel 2: blocks [0, NB_LAMBDA) = lambda arrays (BTILE=16 batch rows each);
// blocks [NB_LAMBDA, NB_LAMBDA+BB) = return_time_pred.
// ---------------------------------------------------------------------------
__global__ void __launch_bounds__(256) main_kernel(float* __restrict__ out)
{
    int bx  = blockIdx.x;
    int tid = threadIdx.x;

    if (bx < NB_LAMBDA) {
        // ------------------------- lambda arrays ---------------------------
        int gx = bx % NBX;
        int gy = bx / NBX;

        __shared__ float4 sBC[BTILE];
        if (tid < BTILE) sBC[tid] = g_bc[gy * BTILE + tid];
        __syncthreads();

        int n4 = gx * 256 + tid;
        if (n4 >= NN / 4) return;

        float4 E0 = g_nodeE[n4 * 4 + 0];
        float4 E1 = g_nodeE[n4 * 4 + 1];
        float4 E2 = g_nodeE[n4 * 4 + 2];
        float4 E3 = g_nodeE[n4 * 4 + 3];

        const size_t dstOff = (size_t)BB * NN;
        const size_t nbase  = (size_t)n4 * 4;
        const int    b0     = gy * BTILE;

        #pragma unroll 4
        for (int j = 0; j < BTILE; j++) {
            float4 bc = sBC[j];
            float pl   = bc.z;
            bool  e    = (pl < 0.0f);
            float psln = fabsf(pl);
            float Ecs  = bc.x, Ecd = bc.y;

            float4 rs, rd;
            {
                float Ev = e ? E0.w : E0.z, Eu = e ? E0.y : E0.x;
                rs.x = psln * __log2f(fmaf(Ecs, Ev, 1.0f));
                rd.x = psln * __log2f(fmaf(Ecd, Eu, 1.0f));
            }
            {
                float Ev = e ? E1.w : E1.z, Eu = e ? E1.y : E1.x;
                rs.y = psln * __log2f(fmaf(Ecs, Ev, 1.0f));
                rd.y = psln * __log2f(fmaf(Ecd, Eu, 1.0f));
            }
            {
                float Ev = e ? E2.w : E2.z, Eu = e ? E2.y : E2.x;
                rs.z = psln * __log2f(fmaf(Ecs, Ev, 1.0f));
                rd.z = psln * __log2f(fmaf(Ecd, Eu, 1.0f));
            }
            {
                float Ev = e ? E3.w : E3.z, Eu = e ? E3.y : E3.x;
                rs.w = psln * __log2f(fmaf(Ecs, Ev, 1.0f));
                rd.w = psln * __log2f(fmaf(Ecd, Eu, 1.0f));
            }

            size_t base = (size_t)(b0 + j) * NN + nbase;
            __stcs((float4*)(out + base), rs);
            __stcs((float4*)(out + dstOff + base), rd);
        }
        return;
    }

    // ------------------- return_time_pred (per-b block scan) ---------------
    int b    = bx - NB_LAMBDA;
    int lane = tid & 31;
    int wid  = tid >> 5;

    __shared__ float warpSums[8];
    __shared__ float sLast;

    float gb = g_gBase[b], al = g_alphaB[b], wt = g_wtB[b];
    float ps = g_psiB[b],  k  = g_kB[b];

    float carry = 0.0f, acc = 0.0f;

    for (int c = 0; c < 4; c++) {
        int   s  = c * 256 + tid;
        float td = (float)s * 0.01f;
        float x = 0.0f, inten = 0.0f;
        if (s < NSAMP) {
            float g  = gb + al * __expf(-wt * (td * (1.0f / 100.0f)));
            float gp = g * k;
            inten = ps * (fmaxf(gp, 0.0f) + __logf(1.0f + __expf(-fabsf(gp))));
            x = 0.01f * inten;
        }
        float v = x;
        #pragma unroll
        for (int off = 1; off < 32; off <<= 1) {
            float t = __shfl_up_sync(0xffffffffu, v, off);
            if (lane >= off) v += t;
        }
        if (lane == 31) warpSums[wid] = v;
        __syncthreads();
        if (tid < 8) {
            float wv = warpSums[tid];
            #pragma unroll
            for (int off = 1; off < 8; off <<= 1) {
                float t = __shfl_up_sync(0xffu, wv, off);
                if (tid >= off) wv += t;
            }
            warpSums[tid] = wv;
        }
        __syncthreads();
        float incl     = v + (wid ? warpSums[wid - 1] : 0.0f);
        float chunkSum = warpSums[7];

        if (s < NSAMP) {
            float integral = carry + incl;
            float density  = inten * __expf(-integral);
            float ts       = td * density;
            acc += ts;
            if (s == NSAMP - 1) sLast = ts;
        }
        carry += chunkSum;
        __syncthreads();
    }

    #pragma unroll
    for (int off = 16; off; off >>= 1)
        acc += __shfl_down_sync(0xffffffffu, acc, off);
    if (lane == 0) warpSums[wid] = acc;
    __syncthreads();
    if (tid == 0) {
        float tot = 0.0f;
        #pragma unroll
        for (int i = 0; i < 8; i++) tot += warpSums[i];
        out[(size_t)2 * BB * NN + b] = 0.01f * (tot - 0.5f * sLast);
    }
}

// ---------------------------------------------------------------------------
extern "C" void kernel_launch(void* const* d_in, const int* in_sizes, int n_in,
                              void* d_out, int out_size)
{
    const float* emb         = (const float*)d_in[0];
    const int*   assoc       = (const int*)  d_in[1];
    const int*   src         = (const int*)  d_in[2];
    const int*   pos_dst     = (const int*)  d_in[3];
    // d_in[4] = neg_dst (unused by reference)
    const float* last_update = (const float*)d_in[5];
    const float* cur_time    = (const float*)d_in[6];
    const int*   et          = (const int*)  d_in[7];
    const float* W           = (const float*)d_in[8];
    const float* bvec        = (const float*)d_in[9];
    const float* psi         = (const float*)d_in[10];
    const float* alpha       = (const float*)d_in[11];
    const float* w_t         = (const float*)d_in[12];

    float* out = (float*)d_out;

    int nodeBlocks = (NN * 8 + 255) / 256;   // 1563 (8 lanes per node)
    int bBlocks    = (BB + 31) / 32;         // 16
    precompute_kernel<<<nodeBlocks + bBlocks, 256>>>(
        emb, assoc, src, pos_dst, last_update, cur_time, et,
        W, bvec, psi, alpha, w_t, nodeBlocks);

    main_kernel<<<NB_LAMBDA + BB, 256>>>(out);
}

// round 9
// speedup vs baseline: 1.3659x; 1.0172x over previous
#include <cuda_runtime.h>
#include <cstdint>

#define NN 50000
#define BB 512
#define DD 32
#define NSAMP 1001
#define BTILE 16
#define NBX 49                    // ceil((NN/4)/256)
#define GYN 32                    // BB / BTILE
#define NB_LAMBDA (NBX * GYN)     // 1568
#define L2E 1.4426950408889634f
#define LN2 0.6931471805599453f

// Scratch (no cudaMalloc allowed)
__device__ float4 g_nodeE[NN];    // (Eu0, Eu1, Ev0, Ev1) = 2^(kl_e * dot)
__device__ float4 g_bcS[BB];      // per-gy-group et-sorted: (Ecs, Ecd, psln, rowByteOff)
__device__ int    g_cnt0[GYN];    // #et==0 rows per group
__device__ float  g_psiB[BB], g_kB[BB];
__device__ float  g_gBase[BB], g_alphaB[BB], g_wtB[BB];

// ---------------------------------------------------------------------------
// Kernel 1: node exp-factors (8 lanes per node) + per-batch constants with
// in-block et-sort (16 bconst blocks of 32 items each).
// ---------------------------------------------------------------------------
__global__ void __launch_bounds__(256) precompute_kernel(
    const float* __restrict__ emb, const int* __restrict__ assoc,
    const int* __restrict__ src, const int* __restrict__ pos_dst,
    const float* __restrict__ last_update, const float* __restrict__ cur_time,
    const int* __restrict__ et, const float* __restrict__ W,
    const float* __restrict__ bvec, const float* __restrict__ psi,
    const float* __restrict__ alpha, const float* __restrict__ w_t,
    int nodeBlocks)
{
    __shared__ float sW[128];
    int tid = threadIdx.x;

    if ((int)blockIdx.x < nodeBlocks) {
        // ------------- node exp-factors: 8 lanes per node ------------------
        if (tid < 128) {
            float kl = L2E / (psi[tid >> 6] + 1e-7f);
            sW[tid] = W[tid] * kl;     // W pre-scaled by k_e * log2(e)
        }
        __syncthreads();

        int g = blockIdx.x * 256 + tid;
        if (g >= NN * 8) return;
        int n = g >> 3;
        int r = g & 7;

        float4 e4 = *(const float4*)(emb + (size_t)n * DD + r * 4);

        const float* w0 = sW +      r * 4;   // Wu0*kl0
        const float* w1 = sW + 64 + r * 4;   // Wu1*kl1
        const float* w2 = sW + 32 + r * 4;   // Wv0*kl0
        const float* w3 = sW + 96 + r * 4;   // Wv1*kl1
        float p0 = e4.x*w0[0] + e4.y*w0[1] + e4.z*w0[2] + e4.w*w0[3];
        float p1 = e4.x*w1[0] + e4.y*w1[1] + e4.z*w1[2] + e4.w*w1[3];
        float p2 = e4.x*w2[0] + e4.y*w2[1] + e4.z*w2[2] + e4.w*w2[3];
        float p3 = e4.x*w3[0] + e4.y*w3[1] + e4.z*w3[2] + e4.w*w3[3];

        #pragma unroll
        for (int off = 1; off <= 4; off <<= 1) {
            p0 += __shfl_xor_sync(0xffffffffu, p0, off);
            p1 += __shfl_xor_sync(0xffffffffu, p1, off);
            p2 += __shfl_xor_sync(0xffffffffu, p2, off);
            p3 += __shfl_xor_sync(0xffffffffu, p3, off);
        }
        if (r < 4) {
            float v = (r == 0) ? p0 : (r == 1) ? p1 : (r == 2) ? p2 : p3;
            ((float*)g_nodeE)[n * 4 + r] = exp2f(v);
        }
    } else {
        // ------------- batch constants + et-sort (32 items/block) ----------
        __shared__ float4 sh_bc[32];
        __shared__ int    sh_et[32];

        if (tid < 128) sW[tid] = W[tid];
        __syncthreads();

        int li  = tid >> 3;                               // local item 0..31
        int idx = (blockIdx.x - nodeBlocks) * 32 + li;    // exact: 16 blocks * 32 = 512
        int r   = tid & 7;

        int e = (et[idx] > 0) ? 1 : 0;
        int s = assoc[src[idx]];
        int d = assoc[pos_dst[idx]];

        float4 zs4 = *(const float4*)(emb + (size_t)s * DD + r * 4);
        float4 zd4 = *(const float4*)(emb + (size_t)d * DD + r * 4);

        const float* Wu = sW + e * 64 + r * 4;
        const float* Wv = sW + e * 64 + 32 + r * 4;
        float dus = zs4.x*Wu[0] + zs4.y*Wu[1] + zs4.z*Wu[2] + zs4.w*Wu[3];
        float dvd = zd4.x*Wv[0] + zd4.y*Wv[1] + zd4.z*Wv[2] + zd4.w*Wv[3];

        #pragma unroll
        for (int off = 1; off <= 4; off <<= 1) {
            dus += __shfl_xor_sync(0xffffffffu, dus, off);
            dvd += __shfl_xor_sync(0xffffffffu, dvd, off);
        }

        if (r == 0) {
            float ct  = cur_time[idx];
            float tds = (ct - last_update[s]) * (1.0f / 100.0f);
            float tdd = (ct - last_update[d]) * (1.0f / 100.0f);
            float be = bvec[e], al = alpha[e], wt = w_t[e], ps = psi[e];
            float k  = 1.0f / (ps + 1e-7f);
            float kl = k * L2E;
            float cs = dus + be + al * expf(-wt * tds);
            float cd = dvd + be + al * expf(-wt * tdd);

            sh_bc[li] = make_float4(exp2f(kl * cs), exp2f(kl * cd),
                                    ps * LN2, __int_as_float(idx * (NN * 4)));
            sh_et[li] = e;

            g_gBase[idx]  = dus + dvd + be;
            g_psiB[idx]   = ps;
            g_kB[idx]     = k;
            g_alphaB[idx] = al;
            g_wtB[idx]    = wt;
        }
        __syncthreads();

        if (tid < 32) {
            int ee = sh_et[tid];
            unsigned bal = __ballot_sync(0xffffffffu, ee == 0);
            int grp = tid >> 4, l = tid & 15;
            unsigned m = (bal >> (grp * 16)) & 0xFFFFu;
            int cnt0 = __popc(m);
            unsigned lower = (1u << l) - 1u;
            int pos = (ee == 0) ? __popc(m & lower)
                                : cnt0 + __popc((~m) & 0xFFFFu & lower);
            int gyIdx = (((blockIdx.x - nodeBlocks) * 32) + tid) >> 4;
            g_bcS[gyIdx * 16 + pos] = sh_bc[tid];
            if (l == 0) g_cnt0[gyIdx] = cnt0;
        }
    }
}

// ---------------------------------------------------------------------------
// Lambda row emitter for an et-uniform run of rows. Zero SELs: Eu/Ev picked
// at compile time by the caller.
// ---------------------------------------------------------------------------
__device__ __forceinline__ void emit_rows(
    const float4* __restrict__ sBC, int jbeg, int jend,
    float Eu0, float Eu1, float Eu2, float Eu3,
    float Ev0, float Ev1, float Ev2, float Ev3,
    char* obase)
{
    #pragma unroll 2
    for (int j = jbeg; j < jend; j++) {
        float4 bc = sBC[j];
        float Ecs = bc.x, Ecd = bc.y, psln = bc.z;
        int rowOff = __float_as_int(bc.w);
        float4 rs, rd;
        rs.x = psln * __log2f(fmaf(Ecs, Ev0, 1.0f));
        rs.y = psln * __log2f(fmaf(Ecs, Ev1, 1.0f));
        rs.z = psln * __log2f(fmaf(Ecs, Ev2, 1.0f));
        rs.w = psln * __log2f(fmaf(Ecs, Ev3, 1.0f));
        rd.x = psln * __log2f(fmaf(Ecd, Eu0, 1.0f));
        rd.y = psln * __log2f(fmaf(Ecd, Eu1, 1.0f));
        rd.z = psln * __log2f(fmaf(Ecd, Eu2, 1.0f));
        rd.w = psln * __log2f(fmaf(Ecd, Eu3, 1.0f));
        char* p = obase + rowOff;
        __stcs((float4*)p, rs);
        __stcs((float4*)(p + (size_t)BB * NN * 4), rd);
    }
}

// ---------------------------------------------------------------------------
// Kernel 2: blocks [0, BB) = return_time_pred (scheduled first, hides under
// lambda); blocks [BB, BB+NB_LAMBDA) = lambda arrays.
// ---------------------------------------------------------------------------
__global__ void __launch_bounds__(256) main_kernel(float* __restrict__ out)
{
    int bx  = blockIdx.x;
    int tid = threadIdx.x;

    if (bx >= BB) {
        // ------------------------- lambda arrays ---------------------------
        int lb = bx - BB;
        int gx = lb % NBX;
        int gy = lb / NBX;

        __shared__ float4 sBC[BTILE];
        __shared__ int sCnt;
        if (tid < BTILE) sBC[tid] = g_bcS[gy * BTILE + tid];
        if (tid == 0) sCnt = g_cnt0[gy];
        __syncthreads();

        int n4 = gx * 256 + tid;
        if (n4 >= NN / 4) return;
        int cnt0 = sCnt;

        float4 E0 = g_nodeE[n4 * 4 + 0];
        float4 E1 = g_nodeE[n4 * 4 + 1];
        float4 E2 = g_nodeE[n4 * 4 + 2];
        float4 E3 = g_nodeE[n4 * 4 + 3];

        char* obase = (char*)out + (size_t)n4 * 16;

        // et == 0 rows: Eu = .x, Ev = .z
        emit_rows(sBC, 0, cnt0,
                  E0.x, E1.x, E2.x, E3.x,
                  E0.z, E1.z, E2.z, E3.z, obase);
        // et == 1 rows: Eu = .y, Ev = .w
        emit_rows(sBC, cnt0, BTILE,
                  E0.y, E1.y, E2.y, E3.y,
                  E0.w, E1.w, E2.w, E3.w, obase);
        return;
    }

    // ------------------- return_time_pred (per-b block scan) ---------------
    int b    = bx;
    int lane = tid & 31;
    int wid  = tid >> 5;

    __shared__ float warpSums[8];
    __shared__ float sLast;

    float gb = g_gBase[b], al = g_alphaB[b], wt = g_wtB[b];
    float ps = g_psiB[b],  k  = g_kB[b];

    float carry = 0.0f, acc = 0.0f;

    for (int c = 0; c < 4; c++) {
        int   s  = c * 256 + tid;
        float td = (float)s * 0.01f;
        float x = 0.0f, inten = 0.0f;
        if (s < NSAMP) {
            float g  = gb + al * __expf(-wt * (td * (1.0f / 100.0f)));
            float gp = g * k;
            inten = ps * (fmaxf(gp, 0.0f) + __logf(1.0f + __expf(-fabsf(gp))));
            x = 0.01f * inten;
        }
        float v = x;
        #pragma unroll
        for (int off = 1; off < 32; off <<= 1) {
            float t = __shfl_up_sync(0xffffffffu, v, off);
            if (lane >= off) v += t;
        }
        if (lane == 31) warpSums[wid] = v;
        __syncthreads();
        if (tid < 8) {
            float wv = warpSums[tid];
            #pragma unroll
            for (int off = 1; off < 8; off <<= 1) {
                float t = __shfl_up_sync(0xffu, wv, off);
                if (tid >= off) wv += t;
            }
            warpSums[tid] = wv;
        }
        __syncthreads();
        float incl     = v + (wid ? warpSums[wid - 1] : 0.0f);
        float chunkSum = warpSums[7];

        if (s < NSAMP) {
            float integral = carry + incl;
            float density  = inten * __expf(-integral);
            float ts       = td * density;
            acc += ts;
            if (s == NSAMP - 1) sLast = ts;
        }
        carry += chunkSum;
        __syncthreads();
    }

    #pragma unroll
    for (int off = 16; off; off >>= 1)
        acc += __shfl_down_sync(0xffffffffu, acc, off);
    if (lane == 0) warpSums[wid] = acc;
    __syncthreads();
    if (tid == 0) {
        float tot = 0.0f;
        #pragma unroll
        for (int i = 0; i < 8; i++) tot += warpSums[i];
        out[(size_t)2 * BB * NN + b] = 0.01f * (tot - 0.5f * sLast);
    }
}

// ---------------------------------------------------------------------------
extern "C" void kernel_launch(void* const* d_in, const int* in_sizes, int n_in,
                              void* d_out, int out_size)
{
    const float* emb         = (const float*)d_in[0];
    const int*   assoc       = (const int*)  d_in[1];
    const int*   src         = (const int*)  d_in[2];
    const int*   pos_dst     = (const int*)  d_in[3];
    // d_in[4] = neg_dst (unused by reference)
    const float* last_update = (const float*)d_in[5];
    const float* cur_time    = (const float*)d_in[6];
    const int*   et          = (const int*)  d_in[7];
    const float* W           = (const float*)d_in[8];
    const float* bvec        = (const float*)d_in[9];
    const float* psi         = (const float*)d_in[10];
    const float* alpha       = (const float*)d_in[11];
    const float* w_t         = (const float*)d_in[12];

    float* out = (float*)d_out;

    int nodeBlocks = (NN * 8 + 255) / 256;   // 1563 (8 lanes per node)
    int bBlocks    = BB / 32;                // 16 (exact)
    precompute_kernel<<<nodeBlocks + bBlocks, 256>>>(
        emb, assoc, src, pos_dst, last_update, cur_time, et,
        W, bvec, psi, alpha, w_t, nodeBlocks);

    main_kernel<<<BB + NB_LAMBDA, 256>>>(out);
}